// round 12
// baseline (speedup 1.0000x reference)
#include <cuda_runtime.h>

#define TPB        256
#define BLK_PER_SM 6
#define NBLOCKS    (152 * BLK_PER_SM)   // 912: one full resident wave on GB300's 152 SMs

__device__ float g_partials[NBLOCKS];
__device__ unsigned int g_count = 0;

__device__ __forceinline__ float bce_elem(float p, float t) {
    // t is exactly 0.0f or 1.0f
    bool one = (t != 0.0f);
    float arg = one ? p : (1.0f - p);
    float w   = one ? 1.6f : 0.4f;
    // -max(log(arg), -100) == min(-log(arg), 100); log(0) -> -inf handled by clamp
    return w * fminf(-__logf(arg), 100.0f);
}

__device__ __forceinline__ float block_reduce(float acc) {
    #pragma unroll
    for (int o = 16; o > 0; o >>= 1)
        acc += __shfl_xor_sync(0xffffffffu, acc, o);
    __shared__ float s[TPB / 32];
    if ((threadIdx.x & 31) == 0) s[threadIdx.x >> 5] = acc;
    __syncthreads();
    float v = 0.0f;
    if (threadIdx.x == 0) {
        #pragma unroll
        for (int w = 0; w < TPB / 32; w++) v += s[w];
    }
    return v;  // valid in thread 0 only
}

__global__ void __launch_bounds__(TPB, BLK_PER_SM)
bce_fused_kernel(const float* __restrict__ pred,
                 const float* __restrict__ targ,
                 float* __restrict__ out,
                 long long n) {
    long long n4 = n >> 2;
    const float4* __restrict__ p4 = (const float4*)pred;
    const float4* __restrict__ t4 = (const float4*)targ;

    float acc = 0.0f;
    const long long stride = (long long)NBLOCKS * TPB;
    long long i = (long long)blockIdx.x * TPB + threadIdx.x;

    // Grid-stride, unrolled x4: 8 float4 streaming loads batched per body.
    // (R10 showed access-pattern shaping doesn't move DRAM%; grid-stride was
    // the measured best — this is R7's loop on the full 152-SM grid.)
    for (; i + 3 * stride < n4; i += 4 * stride) {
        float4 pa = __ldcs(&p4[i]);
        float4 pb = __ldcs(&p4[i + stride]);
        float4 pc = __ldcs(&p4[i + 2 * stride]);
        float4 pd = __ldcs(&p4[i + 3 * stride]);
        float4 ta = __ldcs(&t4[i]);
        float4 tb = __ldcs(&t4[i + stride]);
        float4 tc = __ldcs(&t4[i + 2 * stride]);
        float4 td = __ldcs(&t4[i + 3 * stride]);
        acc += bce_elem(pa.x, ta.x) + bce_elem(pa.y, ta.y)
             + bce_elem(pa.z, ta.z) + bce_elem(pa.w, ta.w);
        acc += bce_elem(pb.x, tb.x) + bce_elem(pb.y, tb.y)
             + bce_elem(pb.z, tb.z) + bce_elem(pb.w, tb.w);
        acc += bce_elem(pc.x, tc.x) + bce_elem(pc.y, tc.y)
             + bce_elem(pc.z, tc.z) + bce_elem(pc.w, tc.w);
        acc += bce_elem(pd.x, td.x) + bce_elem(pd.y, td.y)
             + bce_elem(pd.z, td.z) + bce_elem(pd.w, td.w);
    }
    for (; i < n4; i += stride) {
        float4 p = __ldcs(&p4[i]);
        float4 t = __ldcs(&t4[i]);
        acc += bce_elem(p.x, t.x) + bce_elem(p.y, t.y)
             + bce_elem(p.z, t.z) + bce_elem(p.w, t.w);
    }
    // scalar tail (n % 4)
    if (blockIdx.x == 0) {
        for (long long j = (n4 << 2) + threadIdx.x; j < n; j += TPB)
            acc += bce_elem(pred[j], targ[j]);
    }

    float bsum = block_reduce(acc);

    // Last-block-done final reduction (deterministic order, self-resetting counter)
    __shared__ bool is_last;
    if (threadIdx.x == 0) {
        g_partials[blockIdx.x] = bsum;
        __threadfence();
        unsigned int prev = atomicInc(&g_count, NBLOCKS - 1);
        is_last = (prev == NBLOCKS - 1);
    }
    __syncthreads();

    if (is_last) {
        float a = 0.0f;
        for (int k = threadIdx.x; k < NBLOCKS; k += TPB)
            a += g_partials[k];
        float total = block_reduce(a);
        if (threadIdx.x == 0) out[0] = total;
    }
}

extern "C" void kernel_launch(void* const* d_in, const int* in_sizes, int n_in,
                              void* d_out, int out_size) {
    const float* pred = (const float*)d_in[0];
    const float* targ = (const float*)d_in[1];
    long long n = (long long)in_sizes[0];

    bce_fused_kernel<<<NBLOCKS, TPB>>>(pred, targ, (float*)d_out, n);
}

// round 14
// speedup vs baseline: 1.0057x; 1.0057x over previous
#include <cuda_runtime.h>

#define TPB        256
#define BLK_PER_SM 6
#define NBLOCKS    (148 * BLK_PER_SM)   // 888: R7 config — best measured wall-clock;
                                        // ncu shows 888 vs 912 identical (~86us), so
                                        // keep the empirically best point.

__device__ float g_partials[NBLOCKS];
__device__ unsigned int g_count = 0;

__device__ __forceinline__ float bce_elem(float p, float t) {
    // t is exactly 0.0f or 1.0f
    bool one = (t != 0.0f);
    float arg = one ? p : (1.0f - p);
    float w   = one ? 1.6f : 0.4f;
    // -max(log(arg), -100) == min(-log(arg), 100); log(0) -> -inf handled by clamp
    return w * fminf(-__logf(arg), 100.0f);
}

__device__ __forceinline__ float block_reduce(float acc) {
    #pragma unroll
    for (int o = 16; o > 0; o >>= 1)
        acc += __shfl_xor_sync(0xffffffffu, acc, o);
    __shared__ float s[TPB / 32];
    if ((threadIdx.x & 31) == 0) s[threadIdx.x >> 5] = acc;
    __syncthreads();
    float v = 0.0f;
    if (threadIdx.x == 0) {
        #pragma unroll
        for (int w = 0; w < TPB / 32; w++) v += s[w];
    }
    return v;  // valid in thread 0 only
}

__global__ void __launch_bounds__(TPB, BLK_PER_SM)
bce_fused_kernel(const float* __restrict__ pred,
                 const float* __restrict__ targ,
                 float* __restrict__ out,
                 long long n) {
    long long n4 = n >> 2;
    const float4* __restrict__ p4 = (const float4*)pred;
    const float4* __restrict__ t4 = (const float4*)targ;

    float acc = 0.0f;
    const long long stride = (long long)NBLOCKS * TPB;
    long long i = (long long)blockIdx.x * TPB + threadIdx.x;

    // Grid-stride, unrolled x4: 8 float4 streaming loads front-batched per body.
    // All access-shape variants measure the same ~6.3 TB/s (chip streaming
    // ceiling, pattern-independent) — this is the converged configuration.
    for (; i + 3 * stride < n4; i += 4 * stride) {
        float4 pa = __ldcs(&p4[i]);
        float4 pb = __ldcs(&p4[i + stride]);
        float4 pc = __ldcs(&p4[i + 2 * stride]);
        float4 pd = __ldcs(&p4[i + 3 * stride]);
        float4 ta = __ldcs(&t4[i]);
        float4 tb = __ldcs(&t4[i + stride]);
        float4 tc = __ldcs(&t4[i + 2 * stride]);
        float4 td = __ldcs(&t4[i + 3 * stride]);
        acc += bce_elem(pa.x, ta.x) + bce_elem(pa.y, ta.y)
             + bce_elem(pa.z, ta.z) + bce_elem(pa.w, ta.w);
        acc += bce_elem(pb.x, tb.x) + bce_elem(pb.y, tb.y)
             + bce_elem(pb.z, tb.z) + bce_elem(pb.w, tb.w);
        acc += bce_elem(pc.x, tc.x) + bce_elem(pc.y, tc.y)
             + bce_elem(pc.z, tc.z) + bce_elem(pc.w, tc.w);
        acc += bce_elem(pd.x, td.x) + bce_elem(pd.y, td.y)
             + bce_elem(pd.z, td.z) + bce_elem(pd.w, td.w);
    }
    for (; i < n4; i += stride) {
        float4 p = __ldcs(&p4[i]);
        float4 t = __ldcs(&t4[i]);
        acc += bce_elem(p.x, t.x) + bce_elem(p.y, t.y)
             + bce_elem(p.z, t.z) + bce_elem(p.w, t.w);
    }
    // scalar tail (n % 4)
    if (blockIdx.x == 0) {
        for (long long j = (n4 << 2) + threadIdx.x; j < n; j += TPB)
            acc += bce_elem(pred[j], targ[j]);
    }

    float bsum = block_reduce(acc);

    // Last-block-done final reduction (deterministic order, self-resetting counter)
    __shared__ bool is_last;
    if (threadIdx.x == 0) {
        g_partials[blockIdx.x] = bsum;
        __threadfence();
        unsigned int prev = atomicInc(&g_count, NBLOCKS - 1);
        is_last = (prev == NBLOCKS - 1);
    }
    __syncthreads();

    if (is_last) {
        float a = 0.0f;
        for (int k = threadIdx.x; k < NBLOCKS; k += TPB)
            a += g_partials[k];
        float total = block_reduce(a);
        if (threadIdx.x == 0) out[0] = total;
    }
}

extern "C" void kernel_launch(void* const* d_in, const int* in_sizes, int n_in,
                              void* d_out, int out_size) {
    const float* pred = (const float*)d_in[0];
    const float* targ = (const float*)d_in[1];
    long long n = (long long)in_sizes[0];

    bce_fused_kernel<<<NBLOCKS, TPB>>>(pred, targ, (float*)d_out, n);
}

// round 16
// speedup vs baseline: 1.0541x; 1.0481x over previous
#include <cuda_runtime.h>

#define TPB        256
#define BLK_PER_SM 6
#define NBLOCKS    (148 * BLK_PER_SM)   // 888: best-measured config (R7). All grid/layout
                                        // variants measure 85.7-88.1us ncu-true (noise band
                                        // around the HBM streaming ceiling).

__device__ float g_partials[NBLOCKS];
__device__ unsigned int g_count = 0;

__device__ __forceinline__ float bce_elem(float p, float t) {
    // t is exactly 0.0f or 1.0f
    bool one = (t != 0.0f);
    float arg = one ? p : (1.0f - p);
    float w   = one ? 1.6f : 0.4f;
    // -max(log(arg), -100) == min(-log(arg), 100); log(0) -> -inf handled by clamp
    return w * fminf(-__logf(arg), 100.0f);
}

__device__ __forceinline__ float block_reduce(float acc) {
    #pragma unroll
    for (int o = 16; o > 0; o >>= 1)
        acc += __shfl_xor_sync(0xffffffffu, acc, o);
    __shared__ float s[TPB / 32];
    if ((threadIdx.x & 31) == 0) s[threadIdx.x >> 5] = acc;
    __syncthreads();
    float v = 0.0f;
    if (threadIdx.x == 0) {
        #pragma unroll
        for (int w = 0; w < TPB / 32; w++) v += s[w];
    }
    return v;  // valid in thread 0 only
}

__global__ void __launch_bounds__(TPB, BLK_PER_SM)
bce_fused_kernel(const float* __restrict__ pred,
                 const float* __restrict__ targ,
                 float* __restrict__ out,
                 long long n) {
    long long n4 = n >> 2;
    const float4* __restrict__ p4 = (const float4*)pred;
    const float4* __restrict__ t4 = (const float4*)targ;

    float acc = 0.0f;
    const long long stride = (long long)NBLOCKS * TPB;
    long long i = (long long)blockIdx.x * TPB + threadIdx.x;

    // Grid-stride, unrolled x4: 8 float4 streaming loads front-batched per body.
    // Converged: chip streams ~6.3 TB/s regardless of access shape; this is the
    // measured-best configuration.
    for (; i + 3 * stride < n4; i += 4 * stride) {
        float4 pa = __ldcs(&p4[i]);
        float4 pb = __ldcs(&p4[i + stride]);
        float4 pc = __ldcs(&p4[i + 2 * stride]);
        float4 pd = __ldcs(&p4[i + 3 * stride]);
        float4 ta = __ldcs(&t4[i]);
        float4 tb = __ldcs(&t4[i + stride]);
        float4 tc = __ldcs(&t4[i + 2 * stride]);
        float4 td = __ldcs(&t4[i + 3 * stride]);
        acc += bce_elem(pa.x, ta.x) + bce_elem(pa.y, ta.y)
             + bce_elem(pa.z, ta.z) + bce_elem(pa.w, ta.w);
        acc += bce_elem(pb.x, tb.x) + bce_elem(pb.y, tb.y)
             + bce_elem(pb.z, tb.z) + bce_elem(pb.w, tb.w);
        acc += bce_elem(pc.x, tc.x) + bce_elem(pc.y, tc.y)
             + bce_elem(pc.z, tc.z) + bce_elem(pc.w, tc.w);
        acc += bce_elem(pd.x, td.x) + bce_elem(pd.y, td.y)
             + bce_elem(pd.z, td.z) + bce_elem(pd.w, td.w);
    }
    for (; i < n4; i += stride) {
        float4 p = __ldcs(&p4[i]);
        float4 t = __ldcs(&t4[i]);
        acc += bce_elem(p.x, t.x) + bce_elem(p.y, t.y)
             + bce_elem(p.z, t.z) + bce_elem(p.w, t.w);
    }
    // scalar tail (n % 4)
    if (blockIdx.x == 0) {
        for (long long j = (n4 << 2) + threadIdx.x; j < n; j += TPB)
            acc += bce_elem(pred[j], targ[j]);
    }

    float bsum = block_reduce(acc);

    // Last-block-done final reduction (deterministic order, self-resetting counter)
    __shared__ bool is_last;
    if (threadIdx.x == 0) {
        g_partials[blockIdx.x] = bsum;
        __threadfence();
        unsigned int prev = atomicInc(&g_count, NBLOCKS - 1);
        is_last = (prev == NBLOCKS - 1);
    }
    __syncthreads();

    if (is_last) {
        float a = 0.0f;
        for (int k = threadIdx.x; k < NBLOCKS; k += TPB)
            a += g_partials[k];
        float total = block_reduce(a);
        if (threadIdx.x == 0) out[0] = total;
    }
}

extern "C" void kernel_launch(void* const* d_in, const int* in_sizes, int n_in,
                              void* d_out, int out_size) {
    const float* pred = (const float*)d_in[0];
    const float* targ = (const float*)d_in[1];
    long long n = (long long)in_sizes[0];

    bce_fused_kernel<<<NBLOCKS, TPB>>>(pred, targ, (float*)d_out, n);
}